// round 10
// baseline (speedup 1.0000x reference)
#include <cuda_runtime.h>

#define NN 50000
#define EE 400000
#define HH 128
#define NREL 20
#define CH 512
#define SWP 20   // padded smem row stride (floats)

// Scratch (device globals; no allocation allowed)
__device__ float  g_nd[NREL * NN];         // dst in-degree -> rsqrt-normalized in place
__device__ float2 g_vc[NREL * NN];         // (v_r[s] = sum_e nd[d], out-degree count)
__device__ float  g_ns[NREL * NN];         // ns_r[s] = rsqrt(max(outdeg,1))
__device__ float4 g_u4[5 * NN];            // u packed per dst type: .j = u_{4g+j}[n]
__device__ float4 g_ut4[NREL * NN];        // ut_rp[d] = nd_rp[d] * u4[dst(rp)][d]
__device__ float4 g_wt4[NREL * NN];        // wt_rp[s] = sum_e ut_rp[d]
__device__ float  g_sigma[NREL];           // sigma_r = sum_n u_r[n]
__device__ float  g_y[80 * 768];           // y[(rp*4 + j)][c] = w^T x
__device__ float  g_t[NREL * HH];          // t_r
__device__ float  g_m[HH];                 // unscaled sum over r of t_r @ W2_r

// RELS dst ntype ids (stock=0, financial=1, macro=2, news=3, policy=4)
__constant__ int c_dst[NREL] = {1,2,3,4, 2,0,3,4, 0,1,3,4, 0,1,2,4, 0,2,3,1};
__constant__ int c_inrel[5][4] = {{5,8,12,16},{0,9,13,19},{1,4,14,17},{2,6,10,18},{3,7,11,15}};
__constant__ int c_F[5] = {5,16,21,768,768};

// Streams/events created at process init (before harness memory baseline).
struct AuxStreams {
    cudaStream_t s1;
    cudaEvent_t eg3, eg4, ejoin;
    AuxStreams() {
        cudaStreamCreateWithFlags(&s1, cudaStreamNonBlocking);
        cudaEventCreateWithFlags(&eg3, cudaEventDisableTiming);
        cudaEventCreateWithFlags(&eg4, cudaEventDisableTiming);
        cudaEventCreateWithFlags(&ejoin, cudaEventDisableTiming);
    }
};
static AuxStreams g_aux;

__global__ void k_zero() {
    int i = blockIdx.x * blockDim.x + threadIdx.x;
    int stride = gridDim.x * blockDim.x;
    float4 z = make_float4(0.f, 0.f, 0.f, 0.f);
    for (int k = i; k < (NREL * NN) / 4; k += stride) ((float4*)g_nd)[k] = z;
    for (int k = i; k < (NREL * NN) / 2; k += stride) ((float4*)g_vc)[k] = z;
    for (int k = i; k < NREL * NN; k += stride) g_wt4[k] = z;
    for (int k = i; k < (80 * 768) / 4; k += stride) ((float4*)g_y)[k] = z;
    for (int k = i; k < (NREL * HH) / 4; k += stride) ((float4*)g_t)[k] = z;
    for (int k = i; k < HH / 4; k += stride) ((float4*)g_m)[k] = z;
    if (i < NREL) g_sigma[i] = 0.f;
}

// dst in-degree only (1 RED per edge)
__global__ void k_ddeg(const int* __restrict__ edges) {
    int t = blockIdx.x * blockDim.x + threadIdx.x;
    if (t >= EE / 4) return;
    int r = blockIdx.y;
    const int4* dp = (const int4*)(edges + r * 2 * EE + EE);
    int4 d = dp[t];
    float* dd = g_nd + r * NN;
    atomicAdd(&dd[d.x], 1.f); atomicAdd(&dd[d.y], 1.f);
    atomicAdd(&dd[d.z], 1.f); atomicAdd(&dd[d.w], 1.f);
}

// in-place: nd -> rsqrt(max(nd,1))
__global__ void k_normd() {
    int i = blockIdx.x * blockDim.x + threadIdx.x;
    int stride = gridDim.x * blockDim.x;
    float4* p = (float4*)g_nd;
    for (int k = i; k < (NREL * NN) / 4; k += stride) {
        float4 v = p[k];
        v.x = rsqrtf(fmaxf(v.x, 1.f));
        v.y = rsqrtf(fmaxf(v.y, 1.f));
        v.z = rsqrtf(fmaxf(v.z, 1.f));
        v.w = rsqrtf(fmaxf(v.w, 1.f));
        p[k] = v;
    }
}

// (v,cnt)[s] += (nd[d], 1)
__global__ void k_vpass(const int* __restrict__ edges) {
    int t = blockIdx.x * blockDim.x + threadIdx.x;
    if (t >= EE / 4) return;
    int r = blockIdx.y;
    const int4* sp = (const int4*)(edges + r * 2 * EE);
    const int4* dp = (const int4*)(edges + r * 2 * EE + EE);
    int4 s4 = sp[t], d4 = dp[t];
    const float* nd_ = g_nd + r * NN;
    float2* vc = g_vc + r * NN;
    atomicAdd(&vc[s4.x], make_float2(nd_[d4.x], 1.f));
    atomicAdd(&vc[s4.y], make_float2(nd_[d4.y], 1.f));
    atomicAdd(&vc[s4.z], make_float2(nd_[d4.z], 1.f));
    atomicAdd(&vc[s4.w], make_float2(nd_[d4.w], 1.f));
}

// streaming: ns = rsqrt(max(cnt,1)); u4[g][n].j = ns*v; store ns
__global__ void k_prep() {
    int n = blockIdx.x * blockDim.x + threadIdx.x;
    if (n >= NN) return;
    int g = blockIdx.y;
    float u[4];
#pragma unroll
    for (int j = 0; j < 4; j++) {
        int rp = 4 * g + j;
        float2 vc = g_vc[rp * NN + n];
        float ns = rsqrtf(fmaxf(vc.y, 1.f));
        g_ns[rp * NN + n] = ns;
        u[j] = ns * vc.x;
    }
    g_u4[g * NN + n] = make_float4(u[0], u[1], u[2], u[3]);
}

// ut_rp[n] = nd_rp[n] * u4[dst(rp)][n]
__global__ void k_utld() {
    int n = blockIdx.x * blockDim.x + threadIdx.x;
    if (n >= NN) return;
    int rp = blockIdx.y;
    int dt = c_dst[rp];
    float nd = g_nd[rp * NN + n];
    float4 u = g_u4[dt * NN + n];
    g_ut4[rp * NN + n] = make_float4(nd * u.x, nd * u.y, nd * u.z, nd * u.w);
}

// sigma_{4g+j} = sum_n u4[g][n].j
__global__ void k_sigma() {
    int g = blockIdx.x;
    int i0 = blockIdx.y * 6250;
    int i1 = min(i0 + 6250, NN);
    float4 a = make_float4(0.f, 0.f, 0.f, 0.f);
    for (int i = i0 + threadIdx.x; i < i1; i += blockDim.x) {
        float4 u = g_u4[g * NN + i];
        a.x += u.x; a.y += u.y; a.z += u.z; a.w += u.w;
    }
    __shared__ float4 sred[256];
    sred[threadIdx.x] = a;
    __syncthreads();
    for (int st = 128; st > 0; st >>= 1) {
        if (threadIdx.x < st) {
            float4 b = sred[threadIdx.x + st];
            sred[threadIdx.x].x += b.x; sred[threadIdx.x].y += b.y;
            sred[threadIdx.x].z += b.z; sred[threadIdx.x].w += b.w;
        }
        __syncthreads();
    }
    if (threadIdx.x == 0) {
        float4 s = sred[0];
        atomicAdd(&g_sigma[4 * g + 0], s.x);
        atomicAdd(&g_sigma[4 * g + 1], s.y);
        atomicAdd(&g_sigma[4 * g + 2], s.z);
        atomicAdd(&g_sigma[4 * g + 3], s.w);
    }
}

// wt_rp[s] += ut_rp[d], rp = rbase + blockIdx.y
__global__ void k_wpass(const int* __restrict__ edges, int rbase) {
    int t = blockIdx.x * blockDim.x + threadIdx.x;
    if (t >= EE / 4) return;
    int rp = rbase + blockIdx.y;
    const int4* sp = (const int4*)(edges + rp * 2 * EE);
    const int4* dp = (const int4*)(edges + rp * 2 * EE + EE);
    int4 s4 = sp[t], d4 = dp[t];
    const float4* ut = g_ut4 + rp * NN;
    float4* wt = g_wt4 + rp * NN;
    atomicAdd(&wt[s4.x], ut[d4.x]);
    atomicAdd(&wt[s4.y], ut[d4.y]);
    atomicAdd(&wt[s4.z], ut[d4.z]);
    atomicAdd(&wt[s4.w], ut[d4.w]);
}

__device__ __forceinline__ unsigned long long bcast2(float v) {
    unsigned long long r;
    asm("mov.b64 %0, {%1, %1};" : "=l"(r) : "r"(__float_as_uint(v)));
    return r;
}
__device__ __forceinline__ void fma2(unsigned long long& acc, unsigned long long a,
                                     unsigned long long b) {
    asm("fma.rn.f32x2 %0, %1, %2, %0;" : "+l"(acc) : "l"(a), "l"(b));
}

// y[16S + p][c] += sum_u (ns*wt)[p][u] * x_S[u][c]; f32x2-packed accumulate.
// grid: (1, ceil(NN/CH)); block 256; 4 cols/thread; one S per launch.
__global__ void k_colsum(const float* __restrict__ x, int S, int F) {
    int c0 = threadIdx.x * 4;
    int u0 = blockIdx.y * CH;
    int u1 = min(u0 + CH, NN);
    bool vec = ((F & 3) == 0);
    bool active = (c0 < F);
    __shared__ float sw[64 * SWP];   // [node][16 p], padded row (80B, 16B-aligned)
    // acc2[k*4+c] = packed (acc[p=2k][c], acc[p=2k+1][c]), k=0..7, c=0..3
    unsigned long long acc2[32];
#pragma unroll
    for (int k = 0; k < 32; k++) acc2[k] = 0ull;
    float accs[64];  // scalar fallback path accumulators
    if (!vec) {
#pragma unroll
        for (int k = 0; k < 64; k++) accs[k] = 0.f;
    }
    for (int ub = u0; ub < u1; ub += 64) {
        int cnt = min(64, u1 - ub);
        {
            int i = threadIdx.x;    // rl = i>>6 (4 rels), ii = i&63 (64 nodes)
            int rl = i >> 6, ii = i & 63;
            int rp = 4 * S + rl;
            float4 v = make_float4(0.f, 0.f, 0.f, 0.f);
            if (ii < cnt) {
                int node = ub + ii;
                float ns = g_ns[rp * NN + node];
                float4 wt = g_wt4[rp * NN + node];
                v = make_float4(ns * wt.x, ns * wt.y, ns * wt.z, ns * wt.w);
            }
            *(float4*)&sw[ii * SWP + rl * 4] = v;
        }
        __syncthreads();
        if (active) {
            if (vec) {
                const float* xr = x + (size_t)ub * F + c0;
#pragma unroll 2
                for (int i = 0; i < 64; i++) {
                    if (i >= cnt) break;
                    float4 xv = *(const float4*)(xr + (size_t)i * F);
                    unsigned long long bx0 = bcast2(xv.x);
                    unsigned long long bx1 = bcast2(xv.y);
                    unsigned long long bx2 = bcast2(xv.z);
                    unsigned long long bx3 = bcast2(xv.w);
                    const unsigned long long* sv =
                        (const unsigned long long*)&sw[i * SWP];
#pragma unroll
                    for (int k = 0; k < 8; k++) {
                        unsigned long long s2 = sv[k];
                        fma2(acc2[k * 4 + 0], s2, bx0);
                        fma2(acc2[k * 4 + 1], s2, bx1);
                        fma2(acc2[k * 4 + 2], s2, bx2);
                        fma2(acc2[k * 4 + 3], s2, bx3);
                    }
                }
            } else {
                for (int i = 0; i < cnt; i++) {
                    const float* xr = x + (size_t)(ub + i) * F;
                    float xv[4];
#pragma unroll
                    for (int v2 = 0; v2 < 4; v2++)
                        xv[v2] = (c0 + v2 < F) ? xr[c0 + v2] : 0.f;
#pragma unroll
                    for (int p = 0; p < 16; p++) {
                        float s = sw[i * SWP + p];
                        accs[p * 4 + 0] += s * xv[0];
                        accs[p * 4 + 1] += s * xv[1];
                        accs[p * 4 + 2] += s * xv[2];
                        accs[p * 4 + 3] += s * xv[3];
                    }
                }
            }
        }
        __syncthreads();
    }
    if (active) {
        if (vec) {
#pragma unroll
            for (int k = 0; k < 8; k++) {
#pragma unroll
                for (int c = 0; c < 4; c++) {
                    float2 f = *(float2*)&acc2[k * 4 + c];
                    atomicAdd(&g_y[(16 * S + 2 * k + 0) * 768 + c0 + c], f.x);
                    atomicAdd(&g_y[(16 * S + 2 * k + 1) * 768 + c0 + c], f.y);
                }
            }
        } else {
#pragma unroll
            for (int p = 0; p < 16; p++) {
#pragma unroll
                for (int v2 = 0; v2 < 4; v2++) {
                    if (c0 + v2 < F)
                        atomicAdd(&g_y[(16 * S + p) * 768 + c0 + v2], accs[p * 4 + v2]);
                }
            }
        }
    }
}

// t_r[j] += (y_{(r,rp)} @ W1_{rp})[j] + sigma_r * b1[rp][j]
__global__ void k_combine(const float* __restrict__ w1s, const float* __restrict__ w1f,
                          const float* __restrict__ w1m, const float* __restrict__ w1n,
                          const float* __restrict__ w1p, const float* __restrict__ b1) {
    int r = blockIdx.x, q = blockIdx.y, j = threadIdx.x;
    const float* W1tab[5] = {w1s, w1f, w1m, w1n, w1p};
    int s = r >> 2;
    int rp = c_inrel[s][q];
    int S2 = rp >> 2;
    int F = c_F[S2];
    const float* W1 = W1tab[S2] + (rp & 3) * F * HH;
    const float* y = &g_y[(rp * 4 + (r & 3)) * 768];
    float a = 0.f;
    for (int cc = 0; cc < F; cc++) a += y[cc] * W1[cc * HH + j];
    a += g_sigma[r] * b1[rp * HH + j];
    atomicAdd(&g_t[r * HH + j], a);
}

// g_m[j] += (t_r @ W2_r)[j]
__global__ void k_mpart(const float* __restrict__ W2) {
    int r = blockIdx.x, j = threadIdx.x;
    __shared__ float st[HH];
    st[j] = g_t[r * HH + j];
    __syncthreads();
    const float* W = W2 + r * HH * HH;
    float a = 0.f;
#pragma unroll 4
    for (int k = 0; k < HH; k++) a += st[k] * W[k * HH + j];
    atomicAdd(&g_m[j], a);
}

// m[j] = g_m[j]/(5N) + 0.2*sum_r b2[r][j];  out = [m, m@Wfc + bfc]
__global__ void k_fc(const float* __restrict__ b2, const float* __restrict__ Wfc,
                     const float* __restrict__ bfc, float* __restrict__ out) {
    __shared__ float sm[HH];
    int j = threadIdx.x;
    float bsum = 0.f;
    for (int r = 0; r < NREL; r++) bsum += b2[r * HH + j];
    float m = g_m[j] * (1.f / (5.f * (float)NN)) + bsum * 0.2f;
    sm[j] = m;
    out[j] = m;
    __syncthreads();
    if (j < 10) {
        float o = bfc[j];
        for (int k = 0; k < HH; k++) o += sm[k] * Wfc[k * 10 + j];
        out[HH + j] = o;
    }
}

extern "C" void kernel_launch(void* const* d_in, const int* in_sizes, int n_in,
                              void* d_out, int out_size) {
    const float* xs = (const float*)d_in[0];
    const float* xf = (const float*)d_in[1];
    const float* xm = (const float*)d_in[2];
    const float* xn = (const float*)d_in[3];
    const float* xp = (const float*)d_in[4];
    const float* w1s = (const float*)d_in[5];
    const float* w1f = (const float*)d_in[6];
    const float* w1m = (const float*)d_in[7];
    const float* w1n = (const float*)d_in[8];
    const float* w1p = (const float*)d_in[9];
    const float* b1  = (const float*)d_in[10];
    const float* W2  = (const float*)d_in[11];
    const float* b2  = (const float*)d_in[12];
    const float* Wfc = (const float*)d_in[13];
    const float* bfc = (const float*)d_in[14];
    const int* edges = (const int*)d_in[15];
    float* out = (float*)d_out;

    k_zero<<<2048, 256>>>();

    dim3 ge1((EE / 4 + 255) / 256, NREL);
    k_ddeg<<<ge1, 256>>>(edges);
    k_normd<<<1024, 256>>>();
    k_vpass<<<ge1, 256>>>(edges);

    dim3 gn((NN + 255) / 256, 5);
    k_prep<<<gn, 256>>>();
    dim3 gu((NN + 255) / 256, NREL);
    k_utld<<<gu, 256>>>();
    k_sigma<<<dim3(5, 8), 256>>>();

    // wpass news group first, fork colsum(S=3) onto s1; same for policy group.
    dim3 ge4((EE / 4 + 255) / 256, 4);
    dim3 gc(1, (NN + CH - 1) / CH);

    k_wpass<<<ge4, 256>>>(edges, 12);
    cudaEventRecord(g_aux.eg3, 0);
    cudaStreamWaitEvent(g_aux.s1, g_aux.eg3, 0);
    k_colsum<<<gc, 256, 0, g_aux.s1>>>(xn, 3, 768);

    k_wpass<<<ge4, 256>>>(edges, 16);
    cudaEventRecord(g_aux.eg4, 0);
    cudaStreamWaitEvent(g_aux.s1, g_aux.eg4, 0);
    k_colsum<<<gc, 256, 0, g_aux.s1>>>(xp, 4, 768);
    cudaEventRecord(g_aux.ejoin, g_aux.s1);

    dim3 ge12((EE / 4 + 255) / 256, 12);
    k_wpass<<<ge12, 256>>>(edges, 0);
    k_colsum<<<gc, 256>>>(xs, 0, 5);
    k_colsum<<<gc, 256>>>(xf, 1, 16);
    k_colsum<<<gc, 256>>>(xm, 2, 21);

    cudaStreamWaitEvent(0, g_aux.ejoin, 0);
    k_combine<<<dim3(NREL, 4), HH>>>(w1s, w1f, w1m, w1n, w1p, b1);
    k_mpart<<<NREL, HH>>>(W2);
    k_fc<<<1, HH>>>(b2, Wfc, bfc, out);
}

// round 11
// speedup vs baseline: 1.1244x; 1.1244x over previous
#include <cuda_runtime.h>

#define NN 50000
#define EE 400000
#define HH 128
#define NREL 20
#define CH 256
#define SWP 20   // padded smem row stride (floats)

// Scratch (device globals; no allocation allowed)
__device__ float  g_nd[NREL * NN];         // dst in-degree -> rsqrt-normalized in place
__device__ float2 g_vc[NREL * NN];         // (v_r[s] = sum_e nd[d], out-degree count)
__device__ float  g_ns[NREL * NN];         // ns_r[s] = rsqrt(max(outdeg,1))
__device__ float4 g_u4[5 * NN];            // u packed per dst type: .j = u_{4g+j}[n]
__device__ float4 g_ut4[NREL * NN];        // ut_rp[d] = nd_rp[d] * u4[dst(rp)][d]
__device__ float4 g_wt4[NREL * NN];        // wt_rp[s] = sum_e ut_rp[d]
__device__ float  g_sigma[NREL];           // sigma_r = sum_n u_r[n]
__device__ float  g_y[80 * 768];           // y[(rp*4 + j)][c] = w^T x
__device__ float  g_t[NREL * HH];          // t_r
__device__ float  g_m[HH];                 // unscaled sum over r of t_r @ W2_r

// RELS dst ntype ids (stock=0, financial=1, macro=2, news=3, policy=4)
__constant__ int c_dst[NREL] = {1,2,3,4, 2,0,3,4, 0,1,3,4, 0,1,2,4, 0,2,3,1};
__constant__ int c_inrel[5][4] = {{5,8,12,16},{0,9,13,19},{1,4,14,17},{2,6,10,18},{3,7,11,15}};
__constant__ int c_F[5] = {5,16,21,768,768};

__global__ void k_zero() {
    int i = blockIdx.x * blockDim.x + threadIdx.x;
    int stride = gridDim.x * blockDim.x;
    float4 z = make_float4(0.f, 0.f, 0.f, 0.f);
    for (int k = i; k < (NREL * NN) / 4; k += stride) ((float4*)g_nd)[k] = z;
    for (int k = i; k < (NREL * NN) / 2; k += stride) ((float4*)g_vc)[k] = z;
    for (int k = i; k < NREL * NN; k += stride) g_wt4[k] = z;
    for (int k = i; k < (80 * 768) / 4; k += stride) ((float4*)g_y)[k] = z;
    for (int k = i; k < (NREL * HH) / 4; k += stride) ((float4*)g_t)[k] = z;
    for (int k = i; k < HH / 4; k += stride) ((float4*)g_m)[k] = z;
    if (i < NREL) g_sigma[i] = 0.f;
}

// dst in-degree only (1 RED per edge)
__global__ void k_ddeg(const int* __restrict__ edges) {
    int t = blockIdx.x * blockDim.x + threadIdx.x;
    if (t >= EE / 4) return;
    int r = blockIdx.y;
    const int4* dp = (const int4*)(edges + r * 2 * EE + EE);
    int4 d = dp[t];
    float* dd = g_nd + r * NN;
    atomicAdd(&dd[d.x], 1.f); atomicAdd(&dd[d.y], 1.f);
    atomicAdd(&dd[d.z], 1.f); atomicAdd(&dd[d.w], 1.f);
}

// in-place: nd -> rsqrt(max(nd,1))
__global__ void k_normd() {
    int i = blockIdx.x * blockDim.x + threadIdx.x;
    int stride = gridDim.x * blockDim.x;
    float4* p = (float4*)g_nd;
    for (int k = i; k < (NREL * NN) / 4; k += stride) {
        float4 v = p[k];
        v.x = rsqrtf(fmaxf(v.x, 1.f));
        v.y = rsqrtf(fmaxf(v.y, 1.f));
        v.z = rsqrtf(fmaxf(v.z, 1.f));
        v.w = rsqrtf(fmaxf(v.w, 1.f));
        p[k] = v;
    }
}

// (v,cnt)[s] += (nd[d], 1)
__global__ void k_vpass(const int* __restrict__ edges) {
    int t = blockIdx.x * blockDim.x + threadIdx.x;
    if (t >= EE / 4) return;
    int r = blockIdx.y;
    const int4* sp = (const int4*)(edges + r * 2 * EE);
    const int4* dp = (const int4*)(edges + r * 2 * EE + EE);
    int4 s4 = sp[t], d4 = dp[t];
    const float* nd_ = g_nd + r * NN;
    float2* vc = g_vc + r * NN;
    atomicAdd(&vc[s4.x], make_float2(nd_[d4.x], 1.f));
    atomicAdd(&vc[s4.y], make_float2(nd_[d4.y], 1.f));
    atomicAdd(&vc[s4.z], make_float2(nd_[d4.z], 1.f));
    atomicAdd(&vc[s4.w], make_float2(nd_[d4.w], 1.f));
}

// streaming: ns = rsqrt(max(cnt,1)); u4[g][n].j = ns*v; store ns
__global__ void k_prep() {
    int n = blockIdx.x * blockDim.x + threadIdx.x;
    if (n >= NN) return;
    int g = blockIdx.y;
    float u[4];
#pragma unroll
    for (int j = 0; j < 4; j++) {
        int rp = 4 * g + j;
        float2 vc = g_vc[rp * NN + n];
        float ns = rsqrtf(fmaxf(vc.y, 1.f));
        g_ns[rp * NN + n] = ns;
        u[j] = ns * vc.x;
    }
    g_u4[g * NN + n] = make_float4(u[0], u[1], u[2], u[3]);
}

// ut_rp[n] = nd_rp[n] * u4[dst(rp)][n]
__global__ void k_utld() {
    int n = blockIdx.x * blockDim.x + threadIdx.x;
    if (n >= NN) return;
    int rp = blockIdx.y;
    int dt = c_dst[rp];
    float nd = g_nd[rp * NN + n];
    float4 u = g_u4[dt * NN + n];
    g_ut4[rp * NN + n] = make_float4(nd * u.x, nd * u.y, nd * u.z, nd * u.w);
}

// sigma_{4g+j} = sum_n u4[g][n].j
__global__ void k_sigma() {
    int g = blockIdx.x;
    int i0 = blockIdx.y * 6250;
    int i1 = min(i0 + 6250, NN);
    float4 a = make_float4(0.f, 0.f, 0.f, 0.f);
    for (int i = i0 + threadIdx.x; i < i1; i += blockDim.x) {
        float4 u = g_u4[g * NN + i];
        a.x += u.x; a.y += u.y; a.z += u.z; a.w += u.w;
    }
    __shared__ float4 sred[256];
    sred[threadIdx.x] = a;
    __syncthreads();
    for (int st = 128; st > 0; st >>= 1) {
        if (threadIdx.x < st) {
            float4 b = sred[threadIdx.x + st];
            sred[threadIdx.x].x += b.x; sred[threadIdx.x].y += b.y;
            sred[threadIdx.x].z += b.z; sred[threadIdx.x].w += b.w;
        }
        __syncthreads();
    }
    if (threadIdx.x == 0) {
        float4 s = sred[0];
        atomicAdd(&g_sigma[4 * g + 0], s.x);
        atomicAdd(&g_sigma[4 * g + 1], s.y);
        atomicAdd(&g_sigma[4 * g + 2], s.z);
        atomicAdd(&g_sigma[4 * g + 3], s.w);
    }
}

// wt_rp[s] += ut_rp[d]   (one 16B gather + one 16B RED per edge)
__global__ void k_wpass(const int* __restrict__ edges) {
    int t = blockIdx.x * blockDim.x + threadIdx.x;
    if (t >= EE / 4) return;
    int rp = blockIdx.y;
    const int4* sp = (const int4*)(edges + rp * 2 * EE);
    const int4* dp = (const int4*)(edges + rp * 2 * EE + EE);
    int4 s4 = sp[t], d4 = dp[t];
    const float4* ut = g_ut4 + rp * NN;
    float4* wt = g_wt4 + rp * NN;
    atomicAdd(&wt[s4.x], ut[d4.x]);
    atomicAdd(&wt[s4.y], ut[d4.y]);
    atomicAdd(&wt[s4.z], ut[d4.z]);
    atomicAdd(&wt[s4.w], ut[d4.w]);
}

__device__ __forceinline__ unsigned long long bcast2(float v) {
    unsigned long long r;
    asm("mov.b64 %0, {%1, %1};" : "=l"(r) : "r"(__float_as_uint(v)));
    return r;
}
__device__ __forceinline__ void fma2(unsigned long long& acc, unsigned long long a,
                                     unsigned long long b) {
    asm("fma.rn.f32x2 %0, %1, %2, %0;" : "+l"(acc) : "l"(a), "l"(b));
}

// y[16S + p][c] += sum_u (ns*wt)[p][u] * x_S[u][c]; f32x2-packed accumulate.
// grid: (1, ceil(NN/CH), 5), block 256; 4 cols/thread.
__global__ void k_colsum(const float* __restrict__ xs, const float* __restrict__ xf,
                         const float* __restrict__ xm, const float* __restrict__ xn,
                         const float* __restrict__ xp) {
    int S = blockIdx.z;
    int F = c_F[S];
    const float* xtab[5] = {xs, xf, xm, xn, xp};
    const float* x = xtab[S];
    int c0 = threadIdx.x * 4;
    int u0 = blockIdx.y * CH;
    int u1 = min(u0 + CH, NN);
    bool vec = ((F & 3) == 0);
    bool active = (c0 < F);
    __shared__ float sw[64 * SWP];   // [node][16 p], padded row (80B, 16B-aligned)
    // acc2[k*4+c] = packed (acc[p=2k][c], acc[p=2k+1][c]), k=0..7, c=0..3
    unsigned long long acc2[32];
#pragma unroll
    for (int k = 0; k < 32; k++) acc2[k] = 0ull;
    float accs[64];  // scalar fallback accumulators
    if (!vec) {
#pragma unroll
        for (int k = 0; k < 64; k++) accs[k] = 0.f;
    }
    for (int ub = u0; ub < u1; ub += 64) {
        int cnt = min(64, u1 - ub);
        {
            int i = threadIdx.x;    // rl = i>>6 (4 rels), ii = i&63 (64 nodes)
            int rl = i >> 6, ii = i & 63;
            int rp = 4 * S + rl;
            float4 v = make_float4(0.f, 0.f, 0.f, 0.f);
            if (ii < cnt) {
                int node = ub + ii;
                float ns = g_ns[rp * NN + node];
                float4 wt = g_wt4[rp * NN + node];
                v = make_float4(ns * wt.x, ns * wt.y, ns * wt.z, ns * wt.w);
            }
            *(float4*)&sw[ii * SWP + rl * 4] = v;
        }
        __syncthreads();
        if (active) {
            if (vec) {
                const float* xr = x + (size_t)ub * F + c0;
#pragma unroll 2
                for (int i = 0; i < 64; i++) {
                    if (i >= cnt) break;
                    float4 xv = *(const float4*)(xr + (size_t)i * F);
                    unsigned long long bx0 = bcast2(xv.x);
                    unsigned long long bx1 = bcast2(xv.y);
                    unsigned long long bx2 = bcast2(xv.z);
                    unsigned long long bx3 = bcast2(xv.w);
                    const unsigned long long* sv =
                        (const unsigned long long*)&sw[i * SWP];
#pragma unroll
                    for (int k = 0; k < 8; k++) {
                        unsigned long long s2 = sv[k];
                        fma2(acc2[k * 4 + 0], s2, bx0);
                        fma2(acc2[k * 4 + 1], s2, bx1);
                        fma2(acc2[k * 4 + 2], s2, bx2);
                        fma2(acc2[k * 4 + 3], s2, bx3);
                    }
                }
            } else {
                for (int i = 0; i < cnt; i++) {
                    const float* xr = x + (size_t)(ub + i) * F;
                    float xv[4];
#pragma unroll
                    for (int v2 = 0; v2 < 4; v2++)
                        xv[v2] = (c0 + v2 < F) ? xr[c0 + v2] : 0.f;
#pragma unroll
                    for (int p = 0; p < 16; p++) {
                        float s = sw[i * SWP + p];
                        accs[p * 4 + 0] += s * xv[0];
                        accs[p * 4 + 1] += s * xv[1];
                        accs[p * 4 + 2] += s * xv[2];
                        accs[p * 4 + 3] += s * xv[3];
                    }
                }
            }
        }
        __syncthreads();
    }
    if (active) {
        if (vec) {
#pragma unroll
            for (int k = 0; k < 8; k++) {
#pragma unroll
                for (int c = 0; c < 4; c++) {
                    float2 f = *(float2*)&acc2[k * 4 + c];
                    atomicAdd(&g_y[(16 * S + 2 * k + 0) * 768 + c0 + c], f.x);
                    atomicAdd(&g_y[(16 * S + 2 * k + 1) * 768 + c0 + c], f.y);
                }
            }
        } else {
#pragma unroll
            for (int p = 0; p < 16; p++) {
#pragma unroll
                for (int v2 = 0; v2 < 4; v2++) {
                    if (c0 + v2 < F)
                        atomicAdd(&g_y[(16 * S + p) * 768 + c0 + v2], accs[p * 4 + v2]);
                }
            }
        }
    }
}

// t_r[j] += (y_{(r,rp)} @ W1_{rp})[j] + sigma_r * b1[rp][j]
__global__ void k_combine(const float* __restrict__ w1s, const float* __restrict__ w1f,
                          const float* __restrict__ w1m, const float* __restrict__ w1n,
                          const float* __restrict__ w1p, const float* __restrict__ b1) {
    int r = blockIdx.x, q = blockIdx.y, j = threadIdx.x;
    const float* W1tab[5] = {w1s, w1f, w1m, w1n, w1p};
    int s = r >> 2;
    int rp = c_inrel[s][q];
    int S2 = rp >> 2;
    int F = c_F[S2];
    const float* W1 = W1tab[S2] + (rp & 3) * F * HH;
    const float* y = &g_y[(rp * 4 + (r & 3)) * 768];
    float a = 0.f;
    for (int cc = 0; cc < F; cc++) a += y[cc] * W1[cc * HH + j];
    a += g_sigma[r] * b1[rp * HH + j];
    atomicAdd(&g_t[r * HH + j], a);
}

// g_m[j] += (t_r @ W2_r)[j]
__global__ void k_mpart(const float* __restrict__ W2) {
    int r = blockIdx.x, j = threadIdx.x;
    __shared__ float st[HH];
    st[j] = g_t[r * HH + j];
    __syncthreads();
    const float* W = W2 + r * HH * HH;
    float a = 0.f;
#pragma unroll 4
    for (int k = 0; k < HH; k++) a += st[k] * W[k * HH + j];
    atomicAdd(&g_m[j], a);
}

// m[j] = g_m[j]/(5N) + 0.2*sum_r b2[r][j];  out = [m, m@Wfc + bfc]
__global__ void k_fc(const float* __restrict__ b2, const float* __restrict__ Wfc,
                     const float* __restrict__ bfc, float* __restrict__ out) {
    __shared__ float sm[HH];
    int j = threadIdx.x;
    float bsum = 0.f;
    for (int r = 0; r < NREL; r++) bsum += b2[r * HH + j];
    float m = g_m[j] * (1.f / (5.f * (float)NN)) + bsum * 0.2f;
    sm[j] = m;
    out[j] = m;
    __syncthreads();
    if (j < 10) {
        float o = bfc[j];
        for (int k = 0; k < HH; k++) o += sm[k] * Wfc[k * 10 + j];
        out[HH + j] = o;
    }
}

extern "C" void kernel_launch(void* const* d_in, const int* in_sizes, int n_in,
                              void* d_out, int out_size) {
    const float* xs = (const float*)d_in[0];
    const float* xf = (const float*)d_in[1];
    const float* xm = (const float*)d_in[2];
    const float* xn = (const float*)d_in[3];
    const float* xp = (const float*)d_in[4];
    const float* w1s = (const float*)d_in[5];
    const float* w1f = (const float*)d_in[6];
    const float* w1m = (const float*)d_in[7];
    const float* w1n = (const float*)d_in[8];
    const float* w1p = (const float*)d_in[9];
    const float* b1  = (const float*)d_in[10];
    const float* W2  = (const float*)d_in[11];
    const float* b2  = (const float*)d_in[12];
    const float* Wfc = (const float*)d_in[13];
    const float* bfc = (const float*)d_in[14];
    const int* edges = (const int*)d_in[15];
    float* out = (float*)d_out;

    k_zero<<<2048, 256>>>();

    dim3 ge((EE / 4 + 255) / 256, NREL);
    k_ddeg<<<ge, 256>>>(edges);
    k_normd<<<1024, 256>>>();
    k_vpass<<<ge, 256>>>(edges);

    dim3 gn((NN + 255) / 256, 5);
    k_prep<<<gn, 256>>>();
    dim3 gu((NN + 255) / 256, NREL);
    k_utld<<<gu, 256>>>();
    k_sigma<<<dim3(5, 8), 256>>>();

    k_wpass<<<ge, 256>>>(edges);

    dim3 gc(1, (NN + CH - 1) / CH, 5);
    k_colsum<<<gc, 256>>>(xs, xf, xm, xn, xp);

    k_combine<<<dim3(NREL, 4), HH>>>(w1s, w1f, w1m, w1n, w1p, b1);
    k_mpart<<<NREL, HH>>>(W2);
    k_fc<<<1, HH>>>(b2, Wfc, bfc, out);
}

// round 12
// speedup vs baseline: 1.3365x; 1.1887x over previous
#include <cuda_runtime.h>

#define NN 50000
#define EE 400000
#define HH 128
#define NREL 20
#define CH 256
#define SWP 20   // padded smem row stride (floats)

// Scratch (device globals; no allocation allowed)
__device__ float  g_nd[NREL * NN];         // dst in-degree -> rsqrt-normalized in place
__device__ float2 g_vc[NREL * NN];         // (v_r[s] = sum_e nd[d], out-degree count)
__device__ float  g_ns[NREL * NN];         // ns_r[s] = rsqrt(max(outdeg,1))
__device__ float4 g_u4[5 * NN];            // u packed per dst type: .j = u_{4g+j}[n]
__device__ float4 g_ut4[NREL * NN];        // ut_rp[d] = nd_rp[d] * u4[dst(rp)][d]
__device__ float4 g_wt4[NREL * NN];        // wt_rp[s] = sum_e ut_rp[d]
__device__ float  g_sigma[NREL];           // sigma_r = sum_n u_r[n]
__device__ float  g_y[80 * 768];           // y[(rp*4 + j)][c] = w^T x
__device__ float  g_t[NREL * HH];          // t_r
__device__ float  g_m[HH];                 // unscaled sum over r of t_r @ W2_r

// RELS dst ntype ids (stock=0, financial=1, macro=2, news=3, policy=4)
__constant__ int c_dst[NREL] = {1,2,3,4, 2,0,3,4, 0,1,3,4, 0,1,2,4, 0,2,3,1};
__constant__ int c_inrel[5][4] = {{5,8,12,16},{0,9,13,19},{1,4,14,17},{2,6,10,18},{3,7,11,15}};
__constant__ int c_F[5] = {5,16,21,768,768};

__global__ void k_zero() {
    int i = blockIdx.x * blockDim.x + threadIdx.x;
    int stride = gridDim.x * blockDim.x;
    float4 z = make_float4(0.f, 0.f, 0.f, 0.f);
    for (int k = i; k < (NREL * NN) / 4; k += stride) ((float4*)g_nd)[k] = z;
    for (int k = i; k < (NREL * NN) / 2; k += stride) ((float4*)g_vc)[k] = z;
    for (int k = i; k < NREL * NN; k += stride) g_wt4[k] = z;
    for (int k = i; k < (80 * 768) / 4; k += stride) ((float4*)g_y)[k] = z;
    for (int k = i; k < (NREL * HH) / 4; k += stride) ((float4*)g_t)[k] = z;
    for (int k = i; k < HH / 4; k += stride) ((float4*)g_m)[k] = z;
    if (i < NREL) g_sigma[i] = 0.f;
}

// dst in-degree only (1 RED per edge)
__global__ void k_ddeg(const int* __restrict__ edges) {
    int t = blockIdx.x * blockDim.x + threadIdx.x;
    if (t >= EE / 4) return;
    int r = blockIdx.y;
    const int4* dp = (const int4*)(edges + r * 2 * EE + EE);
    int4 d = dp[t];
    float* dd = g_nd + r * NN;
    atomicAdd(&dd[d.x], 1.f); atomicAdd(&dd[d.y], 1.f);
    atomicAdd(&dd[d.z], 1.f); atomicAdd(&dd[d.w], 1.f);
}

// in-place: nd -> rsqrt(max(nd,1))
__global__ void k_normd() {
    int i = blockIdx.x * blockDim.x + threadIdx.x;
    int stride = gridDim.x * blockDim.x;
    float4* p = (float4*)g_nd;
    for (int k = i; k < (NREL * NN) / 4; k += stride) {
        float4 v = p[k];
        v.x = rsqrtf(fmaxf(v.x, 1.f));
        v.y = rsqrtf(fmaxf(v.y, 1.f));
        v.z = rsqrtf(fmaxf(v.z, 1.f));
        v.w = rsqrtf(fmaxf(v.w, 1.f));
        p[k] = v;
    }
}

// (v,cnt)[s] += (nd[d], 1)
__global__ void k_vpass(const int* __restrict__ edges) {
    int t = blockIdx.x * blockDim.x + threadIdx.x;
    if (t >= EE / 4) return;
    int r = blockIdx.y;
    const int4* sp = (const int4*)(edges + r * 2 * EE);
    const int4* dp = (const int4*)(edges + r * 2 * EE + EE);
    int4 s4 = sp[t], d4 = dp[t];
    const float* nd_ = g_nd + r * NN;
    float2* vc = g_vc + r * NN;
    atomicAdd(&vc[s4.x], make_float2(nd_[d4.x], 1.f));
    atomicAdd(&vc[s4.y], make_float2(nd_[d4.y], 1.f));
    atomicAdd(&vc[s4.z], make_float2(nd_[d4.z], 1.f));
    atomicAdd(&vc[s4.w], make_float2(nd_[d4.w], 1.f));
}

// streaming: ns = rsqrt(max(cnt,1)); u4[g][n].j = ns*v; store ns
__global__ void k_prep() {
    int n = blockIdx.x * blockDim.x + threadIdx.x;
    if (n >= NN) return;
    int g = blockIdx.y;
    float u[4];
#pragma unroll
    for (int j = 0; j < 4; j++) {
        int rp = 4 * g + j;
        float2 vc = g_vc[rp * NN + n];
        float ns = rsqrtf(fmaxf(vc.y, 1.f));
        g_ns[rp * NN + n] = ns;
        u[j] = ns * vc.x;
    }
    g_u4[g * NN + n] = make_float4(u[0], u[1], u[2], u[3]);
}

// ut_rp[n] = nd_rp[n] * u4[dst(rp)][n]
__global__ void k_utld() {
    int n = blockIdx.x * blockDim.x + threadIdx.x;
    if (n >= NN) return;
    int rp = blockIdx.y;
    int dt = c_dst[rp];
    float nd = g_nd[rp * NN + n];
    float4 u = g_u4[dt * NN + n];
    g_ut4[rp * NN + n] = make_float4(nd * u.x, nd * u.y, nd * u.z, nd * u.w);
}

// sigma_{4g+j} = sum_n u4[g][n].j
__global__ void k_sigma() {
    int g = blockIdx.x;
    int i0 = blockIdx.y * 6250;
    int i1 = min(i0 + 6250, NN);
    float4 a = make_float4(0.f, 0.f, 0.f, 0.f);
    for (int i = i0 + threadIdx.x; i < i1; i += blockDim.x) {
        float4 u = g_u4[g * NN + i];
        a.x += u.x; a.y += u.y; a.z += u.z; a.w += u.w;
    }
    __shared__ float4 sred[256];
    sred[threadIdx.x] = a;
    __syncthreads();
    for (int st = 128; st > 0; st >>= 1) {
        if (threadIdx.x < st) {
            float4 b = sred[threadIdx.x + st];
            sred[threadIdx.x].x += b.x; sred[threadIdx.x].y += b.y;
            sred[threadIdx.x].z += b.z; sred[threadIdx.x].w += b.w;
        }
        __syncthreads();
    }
    if (threadIdx.x == 0) {
        float4 s = sred[0];
        atomicAdd(&g_sigma[4 * g + 0], s.x);
        atomicAdd(&g_sigma[4 * g + 1], s.y);
        atomicAdd(&g_sigma[4 * g + 2], s.z);
        atomicAdd(&g_sigma[4 * g + 3], s.w);
    }
}

// wt_rp[s] += ut_rp[d]   (one 16B gather + one 16B RED per edge)
__global__ void k_wpass(const int* __restrict__ edges) {
    int t = blockIdx.x * blockDim.x + threadIdx.x;
    if (t >= EE / 4) return;
    int rp = blockIdx.y;
    const int4* sp = (const int4*)(edges + rp * 2 * EE);
    const int4* dp = (const int4*)(edges + rp * 2 * EE + EE);
    int4 s4 = sp[t], d4 = dp[t];
    const float4* ut = g_ut4 + rp * NN;
    float4* wt = g_wt4 + rp * NN;
    atomicAdd(&wt[s4.x], ut[d4.x]);
    atomicAdd(&wt[s4.y], ut[d4.y]);
    atomicAdd(&wt[s4.z], ut[d4.z]);
    atomicAdd(&wt[s4.w], ut[d4.w]);
}

__device__ __forceinline__ unsigned long long bcast2(float v) {
    unsigned long long r;
    asm("mov.b64 %0, {%1, %1};" : "=l"(r) : "r"(__float_as_uint(v)));
    return r;
}
__device__ __forceinline__ void fma2(unsigned long long& acc, unsigned long long a,
                                     unsigned long long b) {
    asm("fma.rn.f32x2 %0, %1, %2, %0;" : "+l"(acc) : "l"(a), "l"(b));
}

// Shared smem-loader: stage (ns*wt) for 64 nodes x 16 p into sw.
__device__ __forceinline__ void load_sw(float* sw, int S, int ub, int cnt) {
    int i = threadIdx.x;    // rl = i>>6 (4 rels), ii = i&63 (64 nodes)
    int rl = i >> 6, ii = i & 63;
    int rp = 4 * S + rl;
    float4 v = make_float4(0.f, 0.f, 0.f, 0.f);
    if (ii < cnt) {
        int node = ub + ii;
        float ns = g_ns[rp * NN + node];
        float4 wt = g_wt4[rp * NN + node];
        v = make_float4(ns * wt.x, ns * wt.y, ns * wt.z, ns * wt.w);
    }
    *(float4*)&sw[ii * SWP + rl * 4] = v;
}

// Big colsum: F=768 (S=3 news via z=0, S=4 policy via z=1). f32x2 packed.
// grid: (1, ceil(NN/CH), 2), block 256; 4 cols/thread (c0 = tid*4 < 768 -> 192 active).
__global__ void k_colsum_big(const float* __restrict__ xn, const float* __restrict__ xp) {
    const int F = 768;
    int S = 3 + blockIdx.z;
    const float* x = blockIdx.z ? xp : xn;
    int c0 = threadIdx.x * 4;
    int u0 = blockIdx.y * CH;
    int u1 = min(u0 + CH, NN);
    bool active = (c0 < F);
    __shared__ float sw[64 * SWP];
    // acc2[k*4+c] = packed (acc[p=2k][c], acc[p=2k+1][c])
    unsigned long long acc2[32];
#pragma unroll
    for (int k = 0; k < 32; k++) acc2[k] = 0ull;
    for (int ub = u0; ub < u1; ub += 64) {
        int cnt = min(64, u1 - ub);
        load_sw(sw, S, ub, cnt);
        __syncthreads();
        if (active) {
            const float* xr = x + (size_t)ub * F + c0;
#pragma unroll 2
            for (int i = 0; i < 64; i++) {
                if (i >= cnt) break;
                float4 xv = *(const float4*)(xr + (size_t)i * F);
                unsigned long long bx0 = bcast2(xv.x);
                unsigned long long bx1 = bcast2(xv.y);
                unsigned long long bx2 = bcast2(xv.z);
                unsigned long long bx3 = bcast2(xv.w);
                const unsigned long long* sv = (const unsigned long long*)&sw[i * SWP];
#pragma unroll
                for (int k = 0; k < 8; k++) {
                    unsigned long long s2 = sv[k];
                    fma2(acc2[k * 4 + 0], s2, bx0);
                    fma2(acc2[k * 4 + 1], s2, bx1);
                    fma2(acc2[k * 4 + 2], s2, bx2);
                    fma2(acc2[k * 4 + 3], s2, bx3);
                }
            }
        }
        __syncthreads();
    }
    if (active) {
#pragma unroll
        for (int k = 0; k < 8; k++) {
#pragma unroll
            for (int c = 0; c < 4; c++) {
                float2 f = *(float2*)&acc2[k * 4 + c];
                atomicAdd(&g_y[(16 * S + 2 * k + 0) * 768 + c0 + c], f.x);
                atomicAdd(&g_y[(16 * S + 2 * k + 1) * 768 + c0 + c], f.y);
            }
        }
    }
}

// Small colsum: S in {0,1,2} (F = 5,16,21), scalar path (tiny data).
// grid: (1, ceil(NN/CH), 3), block 256.
__global__ void k_colsum_small(const float* __restrict__ xs, const float* __restrict__ xf,
                               const float* __restrict__ xm) {
    int S = blockIdx.z;
    int F = c_F[S];
    const float* xtab[3] = {xs, xf, xm};
    const float* x = xtab[S];
    int c0 = threadIdx.x * 4;
    int u0 = blockIdx.y * CH;
    int u1 = min(u0 + CH, NN);
    bool active = (c0 < F);
    __shared__ float sw[64 * SWP];
    float accs[64];
#pragma unroll
    for (int k = 0; k < 64; k++) accs[k] = 0.f;
    for (int ub = u0; ub < u1; ub += 64) {
        int cnt = min(64, u1 - ub);
        load_sw(sw, S, ub, cnt);
        __syncthreads();
        if (active) {
            for (int i = 0; i < cnt; i++) {
                const float* xr = x + (size_t)(ub + i) * F;
                float xv[4];
#pragma unroll
                for (int v2 = 0; v2 < 4; v2++)
                    xv[v2] = (c0 + v2 < F) ? xr[c0 + v2] : 0.f;
#pragma unroll
                for (int p = 0; p < 16; p++) {
                    float s = sw[i * SWP + p];
                    accs[p * 4 + 0] += s * xv[0];
                    accs[p * 4 + 1] += s * xv[1];
                    accs[p * 4 + 2] += s * xv[2];
                    accs[p * 4 + 3] += s * xv[3];
                }
            }
        }
        __syncthreads();
    }
    if (active) {
#pragma unroll
        for (int p = 0; p < 16; p++) {
#pragma unroll
            for (int v2 = 0; v2 < 4; v2++) {
                if (c0 + v2 < F)
                    atomicAdd(&g_y[(16 * S + p) * 768 + c0 + v2], accs[p * 4 + v2]);
            }
        }
    }
}

// t_r[j] += (y_{(r,rp)} @ W1_{rp})[j] + sigma_r * b1[rp][j]
__global__ void k_combine(const float* __restrict__ w1s, const float* __restrict__ w1f,
                          const float* __restrict__ w1m, const float* __restrict__ w1n,
                          const float* __restrict__ w1p, const float* __restrict__ b1) {
    int r = blockIdx.x, q = blockIdx.y, j = threadIdx.x;
    const float* W1tab[5] = {w1s, w1f, w1m, w1n, w1p};
    int s = r >> 2;
    int rp = c_inrel[s][q];
    int S2 = rp >> 2;
    int F = c_F[S2];
    const float* W1 = W1tab[S2] + (rp & 3) * F * HH;
    const float* y = &g_y[(rp * 4 + (r & 3)) * 768];
    float a = 0.f;
    for (int cc = 0; cc < F; cc++) a += y[cc] * W1[cc * HH + j];
    a += g_sigma[r] * b1[rp * HH + j];
    atomicAdd(&g_t[r * HH + j], a);
}

// g_m[j] += (t_r @ W2_r)[j]
__global__ void k_mpart(const float* __restrict__ W2) {
    int r = blockIdx.x, j = threadIdx.x;
    __shared__ float st[HH];
    st[j] = g_t[r * HH + j];
    __syncthreads();
    const float* W = W2 + r * HH * HH;
    float a = 0.f;
#pragma unroll 4
    for (int k = 0; k < HH; k++) a += st[k] * W[k * HH + j];
    atomicAdd(&g_m[j], a);
}

// m[j] = g_m[j]/(5N) + 0.2*sum_r b2[r][j];  out = [m, m@Wfc + bfc]
__global__ void k_fc(const float* __restrict__ b2, const float* __restrict__ Wfc,
                     const float* __restrict__ bfc, float* __restrict__ out) {
    __shared__ float sm[HH];
    int j = threadIdx.x;
    float bsum = 0.f;
    for (int r = 0; r < NREL; r++) bsum += b2[r * HH + j];
    float m = g_m[j] * (1.f / (5.f * (float)NN)) + bsum * 0.2f;
    sm[j] = m;
    out[j] = m;
    __syncthreads();
    if (j < 10) {
        float o = bfc[j];
        for (int k = 0; k < HH; k++) o += sm[k] * Wfc[k * 10 + j];
        out[HH + j] = o;
    }
}

extern "C" void kernel_launch(void* const* d_in, const int* in_sizes, int n_in,
                              void* d_out, int out_size) {
    const float* xs = (const float*)d_in[0];
    const float* xf = (const float*)d_in[1];
    const float* xm = (const float*)d_in[2];
    const float* xn = (const float*)d_in[3];
    const float* xp = (const float*)d_in[4];
    const float* w1s = (const float*)d_in[5];
    const float* w1f = (const float*)d_in[6];
    const float* w1m = (const float*)d_in[7];
    const float* w1n = (const float*)d_in[8];
    const float* w1p = (const float*)d_in[9];
    const float* b1  = (const float*)d_in[10];
    const float* W2  = (const float*)d_in[11];
    const float* b2  = (const float*)d_in[12];
    const float* Wfc = (const float*)d_in[13];
    const float* bfc = (const float*)d_in[14];
    const int* edges = (const int*)d_in[15];
    float* out = (float*)d_out;

    k_zero<<<2048, 256>>>();

    dim3 ge((EE / 4 + 255) / 256, NREL);
    k_ddeg<<<ge, 256>>>(edges);
    k_normd<<<1024, 256>>>();
    k_vpass<<<ge, 256>>>(edges);

    dim3 gn((NN + 255) / 256, 5);
    k_prep<<<gn, 256>>>();
    dim3 gu((NN + 255) / 256, NREL);
    k_utld<<<gu, 256>>>();
    k_sigma<<<dim3(5, 8), 256>>>();

    k_wpass<<<ge, 256>>>(edges);

    dim3 gcb(1, (NN + CH - 1) / CH, 2);
    k_colsum_big<<<gcb, 256>>>(xn, xp);
    dim3 gcs(1, (NN + CH - 1) / CH, 3);
    k_colsum_small<<<gcs, 256>>>(xs, xf, xm);

    k_combine<<<dim3(NREL, 4), HH>>>(w1s, w1f, w1m, w1n, w1p, b1);
    k_mpart<<<NREL, HH>>>(W2);
    k_fc<<<1, HH>>>(b2, Wfc, bfc, out);
}

// round 13
// speedup vs baseline: 1.5733x; 1.1772x over previous
#include <cuda_runtime.h>

#define NN 50000
#define EE 400000
#define HH 128
#define NREL 20
#define CH 128
#define SWP 20   // padded smem row stride (floats)

// Scratch (device globals; no allocation allowed)
__device__ float  g_nd[NREL * NN];         // dst in-degree -> rsqrt-normalized in place
__device__ float2 g_vc[NREL * NN];         // (v_r[s] = sum_e nd[d], out-degree count)
__device__ float  g_ns[NREL * NN];         // ns_r[s] = rsqrt(max(outdeg,1))
__device__ float4 g_ut4[NREL * NN];        // ut_rp[d] = nd_rp[d] * u_{dst group}[d]
__device__ float4 g_wt4[NREL * NN];        // wt_rp[s] = sum_e ut_rp[d]
__device__ float  g_sigma[NREL];           // sigma_r = sum_n u_r[n]
__device__ float  g_y[80 * 768];           // y[(rp*4 + j)][c] = w^T x
__device__ float  g_t[NREL * HH];          // t_r
__device__ float  g_m[HH];                 // unscaled sum over r of t_r @ W2_r

// RELS dst ntype ids (stock=0, financial=1, macro=2, news=3, policy=4)
__constant__ int c_dst[NREL] = {1,2,3,4, 2,0,3,4, 0,1,3,4, 0,1,2,4, 0,2,3,1};
__constant__ int c_inrel[5][4] = {{5,8,12,16},{0,9,13,19},{1,4,14,17},{2,6,10,18},{3,7,11,15}};
__constant__ int c_F[5] = {5,16,21,768,768};

__global__ void k_zero() {
    int i = blockIdx.x * blockDim.x + threadIdx.x;
    int stride = gridDim.x * blockDim.x;
    float4 z = make_float4(0.f, 0.f, 0.f, 0.f);
    for (int k = i; k < (NREL * NN) / 4; k += stride) ((float4*)g_nd)[k] = z;
    for (int k = i; k < (NREL * NN) / 2; k += stride) ((float4*)g_vc)[k] = z;
    for (int k = i; k < NREL * NN; k += stride) g_wt4[k] = z;
    for (int k = i; k < (80 * 768) / 4; k += stride) ((float4*)g_y)[k] = z;
    for (int k = i; k < (NREL * HH) / 4; k += stride) ((float4*)g_t)[k] = z;
    for (int k = i; k < HH / 4; k += stride) ((float4*)g_m)[k] = z;
    if (i < NREL) g_sigma[i] = 0.f;
}

// dst in-degree only (1 RED per edge)
__global__ void k_ddeg(const int* __restrict__ edges) {
    int t = blockIdx.x * blockDim.x + threadIdx.x;
    if (t >= EE / 4) return;
    int r = blockIdx.y;
    const int4* dp = (const int4*)(edges + r * 2 * EE + EE);
    int4 d = dp[t];
    float* dd = g_nd + r * NN;
    atomicAdd(&dd[d.x], 1.f); atomicAdd(&dd[d.y], 1.f);
    atomicAdd(&dd[d.z], 1.f); atomicAdd(&dd[d.w], 1.f);
}

// in-place: nd -> rsqrt(max(nd,1))  (per-node MUFU, cheap; per-edge would cost 63us)
__global__ void k_normd() {
    int i = blockIdx.x * blockDim.x + threadIdx.x;
    int stride = gridDim.x * blockDim.x;
    float4* p = (float4*)g_nd;
    for (int k = i; k < (NREL * NN) / 4; k += stride) {
        float4 v = p[k];
        v.x = rsqrtf(fmaxf(v.x, 1.f));
        v.y = rsqrtf(fmaxf(v.y, 1.f));
        v.z = rsqrtf(fmaxf(v.z, 1.f));
        v.w = rsqrtf(fmaxf(v.w, 1.f));
        p[k] = v;
    }
}

// (v,cnt)[s] += (nd[d], 1)
__global__ void k_vpass(const int* __restrict__ edges) {
    int t = blockIdx.x * blockDim.x + threadIdx.x;
    if (t >= EE / 4) return;
    int r = blockIdx.y;
    const int4* sp = (const int4*)(edges + r * 2 * EE);
    const int4* dp = (const int4*)(edges + r * 2 * EE + EE);
    int4 s4 = sp[t], d4 = dp[t];
    const float* nd_ = g_nd + r * NN;
    float2* vc = g_vc + r * NN;
    atomicAdd(&vc[s4.x], make_float2(nd_[d4.x], 1.f));
    atomicAdd(&vc[s4.y], make_float2(nd_[d4.y], 1.f));
    atomicAdd(&vc[s4.z], make_float2(nd_[d4.z], 1.f));
    atomicAdd(&vc[s4.w], make_float2(nd_[d4.w], 1.f));
}

// Fused per-node prep: ns, u (local), ut4, and sigma (warp+block reduce).
// grid: ceil(NN/256), block 256.
__global__ void k_nodeprep() {
    int n = blockIdx.x * blockDim.x + threadIdx.x;
    bool valid = (n < NN);
    float u[NREL];
    // u_{4g+j}[n] = ns*v ; also store ns for colsum
    if (valid) {
#pragma unroll
        for (int rp = 0; rp < NREL; rp++) {
            float2 vc = g_vc[rp * NN + n];
            float ns = rsqrtf(fmaxf(vc.y, 1.f));
            g_ns[rp * NN + n] = ns;
            u[rp] = ns * vc.x;
        }
        // ut_rp[n] = nd_rp[n] * u4[dst(rp)][n]
#pragma unroll
        for (int rp = 0; rp < NREL; rp++) {
            float nd = g_nd[rp * NN + n];
            int dt = c_dst[rp];
            g_ut4[rp * NN + n] = make_float4(nd * u[4 * dt + 0], nd * u[4 * dt + 1],
                                             nd * u[4 * dt + 2], nd * u[4 * dt + 3]);
        }
    } else {
#pragma unroll
        for (int rp = 0; rp < NREL; rp++) u[rp] = 0.f;
    }
    // sigma: warp shuffle reduce each rel, then block reduce, then 20 atomics.
    __shared__ float ssig[8][NREL];
    int lane = threadIdx.x & 31, wid = threadIdx.x >> 5;
#pragma unroll
    for (int rp = 0; rp < NREL; rp++) {
        float a = u[rp];
        a += __shfl_down_sync(0xffffffff, a, 16);
        a += __shfl_down_sync(0xffffffff, a, 8);
        a += __shfl_down_sync(0xffffffff, a, 4);
        a += __shfl_down_sync(0xffffffff, a, 2);
        a += __shfl_down_sync(0xffffffff, a, 1);
        if (lane == 0) ssig[wid][rp] = a;
    }
    __syncthreads();
    if (threadIdx.x < NREL) {
        float a = 0.f;
#pragma unroll
        for (int w = 0; w < 8; w++) a += ssig[w][threadIdx.x];
        atomicAdd(&g_sigma[threadIdx.x], a);
    }
}

// wt_rp[s] += ut_rp[d]   (one 16B gather + one 16B RED per edge)
__global__ void k_wpass(const int* __restrict__ edges) {
    int t = blockIdx.x * blockDim.x + threadIdx.x;
    if (t >= EE / 4) return;
    int rp = blockIdx.y;
    const int4* sp = (const int4*)(edges + rp * 2 * EE);
    const int4* dp = (const int4*)(edges + rp * 2 * EE + EE);
    int4 s4 = sp[t], d4 = dp[t];
    const float4* ut = g_ut4 + rp * NN;
    float4* wt = g_wt4 + rp * NN;
    atomicAdd(&wt[s4.x], ut[d4.x]);
    atomicAdd(&wt[s4.y], ut[d4.y]);
    atomicAdd(&wt[s4.z], ut[d4.z]);
    atomicAdd(&wt[s4.w], ut[d4.w]);
}

// y[16S + p][c] += sum_u (ns*wt)[p][u] * x_S[u][c]; ns folded in the smem loader.
// grid: (1, ceil(NN/CH), 5), block 256; 4 cols/thread. Scalar inner loop (R8 form).
__global__ void k_colsum(const float* __restrict__ xs, const float* __restrict__ xf,
                         const float* __restrict__ xm, const float* __restrict__ xn,
                         const float* __restrict__ xp) {
    int S = blockIdx.z;
    int F = c_F[S];
    const float* xtab[5] = {xs, xf, xm, xn, xp};
    const float* x = xtab[S];
    int c0 = threadIdx.x * 4;
    int u0 = blockIdx.y * CH;
    int u1 = min(u0 + CH, NN);
    bool vec = ((F & 3) == 0);
    bool active = (c0 < F);
    __shared__ float sw[64 * SWP];   // [node][16 p], padded row
    float acc[64];
#pragma unroll
    for (int k = 0; k < 64; k++) acc[k] = 0.f;
    for (int ub = u0; ub < u1; ub += 64) {
        int cnt = min(64, u1 - ub);
        {
            int i = threadIdx.x;    // rl = i>>6 (4 rels), ii = i&63 (64 nodes)
            int rl = i >> 6, ii = i & 63;
            int rp = 4 * S + rl;
            float4 v = make_float4(0.f, 0.f, 0.f, 0.f);
            if (ii < cnt) {
                int node = ub + ii;
                float ns = g_ns[rp * NN + node];
                float4 wt = g_wt4[rp * NN + node];
                v = make_float4(ns * wt.x, ns * wt.y, ns * wt.z, ns * wt.w);
            }
            *(float4*)&sw[ii * SWP + rl * 4] = v;
        }
        __syncthreads();
        if (active) {
            if (vec) {
                const float* xr = x + (size_t)ub * F + c0;
#pragma unroll 2
                for (int i = 0; i < 64; i++) {
                    if (i >= cnt) break;
                    float4 xv = *(const float4*)(xr + (size_t)i * F);
                    const float4* swr = (const float4*)&sw[i * SWP];
#pragma unroll
                    for (int pg = 0; pg < 4; pg++) {
                        float4 s4 = swr[pg];
                        float sv[4] = {s4.x, s4.y, s4.z, s4.w};
#pragma unroll
                        for (int q = 0; q < 4; q++) {
                            int p = pg * 4 + q;
                            acc[p * 4 + 0] += sv[q] * xv.x;
                            acc[p * 4 + 1] += sv[q] * xv.y;
                            acc[p * 4 + 2] += sv[q] * xv.z;
                            acc[p * 4 + 3] += sv[q] * xv.w;
                        }
                    }
                }
            } else {
                for (int i = 0; i < cnt; i++) {
                    const float* xr = x + (size_t)(ub + i) * F;
                    float xv[4];
#pragma unroll
                    for (int v2 = 0; v2 < 4; v2++)
                        xv[v2] = (c0 + v2 < F) ? xr[c0 + v2] : 0.f;
#pragma unroll
                    for (int p = 0; p < 16; p++) {
                        float s = sw[i * SWP + p];
                        acc[p * 4 + 0] += s * xv[0];
                        acc[p * 4 + 1] += s * xv[1];
                        acc[p * 4 + 2] += s * xv[2];
                        acc[p * 4 + 3] += s * xv[3];
                    }
                }
            }
        }
        __syncthreads();
    }
    if (active) {
#pragma unroll
        for (int p = 0; p < 16; p++) {
#pragma unroll
            for (int v2 = 0; v2 < 4; v2++) {
                if (c0 + v2 < F)
                    atomicAdd(&g_y[(16 * S + p) * 768 + c0 + v2], acc[p * 4 + v2]);
            }
        }
    }
}

// t_r[j] += (y_{(r,rp)} @ W1_{rp})[j] + sigma_r * b1[rp][j]
__global__ void k_combine(const float* __restrict__ w1s, const float* __restrict__ w1f,
                          const float* __restrict__ w1m, const float* __restrict__ w1n,
                          const float* __restrict__ w1p, const float* __restrict__ b1) {
    int r = blockIdx.x, q = blockIdx.y, j = threadIdx.x;
    const float* W1tab[5] = {w1s, w1f, w1m, w1n, w1p};
    int s = r >> 2;
    int rp = c_inrel[s][q];
    int S2 = rp >> 2;
    int F = c_F[S2];
    const float* W1 = W1tab[S2] + (rp & 3) * F * HH;
    const float* y = &g_y[(rp * 4 + (r & 3)) * 768];
    float a = 0.f;
    for (int cc = 0; cc < F; cc++) a += y[cc] * W1[cc * HH + j];
    a += g_sigma[r] * b1[rp * HH + j];
    atomicAdd(&g_t[r * HH + j], a);
}

// g_m[j] += (t_r @ W2_r)[j]
__global__ void k_mpart(const float* __restrict__ W2) {
    int r = blockIdx.x, j = threadIdx.x;
    __shared__ float st[HH];
    st[j] = g_t[r * HH + j];
    __syncthreads();
    const float* W = W2 + r * HH * HH;
    float a = 0.f;
#pragma unroll 4
    for (int k = 0; k < HH; k++) a += st[k] * W[k * HH + j];
    atomicAdd(&g_m[j], a);
}

// m[j] = g_m[j]/(5N) + 0.2*sum_r b2[r][j];  out = [m, m@Wfc + bfc]
__global__ void k_fc(const float* __restrict__ b2, const float* __restrict__ Wfc,
                     const float* __restrict__ bfc, float* __restrict__ out) {
    __shared__ float sm[HH];
    int j = threadIdx.x;
    float bsum = 0.f;
    for (int r = 0; r < NREL; r++) bsum += b2[r * HH + j];
    float m = g_m[j] * (1.f / (5.f * (float)NN)) + bsum * 0.2f;
    sm[j] = m;
    out[j] = m;
    __syncthreads();
    if (j < 10) {
        float o = bfc[j];
        for (int k = 0; k < HH; k++) o += sm[k] * Wfc[k * 10 + j];
        out[HH + j] = o;
    }
}

extern "C" void kernel_launch(void* const* d_in, const int* in_sizes, int n_in,
                              void* d_out, int out_size) {
    const float* xs = (const float*)d_in[0];
    const float* xf = (const float*)d_in[1];
    const float* xm = (const float*)d_in[2];
    const float* xn = (const float*)d_in[3];
    const float* xp = (const float*)d_in[4];
    const float* w1s = (const float*)d_in[5];
    const float* w1f = (const float*)d_in[6];
    const float* w1m = (const float*)d_in[7];
    const float* w1n = (const float*)d_in[8];
    const float* w1p = (const float*)d_in[9];
    const float* b1  = (const float*)d_in[10];
    const float* W2  = (const float*)d_in[11];
    const float* b2  = (const float*)d_in[12];
    const float* Wfc = (const float*)d_in[13];
    const float* bfc = (const float*)d_in[14];
    const int* edges = (const int*)d_in[15];
    float* out = (float*)d_out;

    k_zero<<<2048, 256>>>();

    dim3 ge((EE / 4 + 255) / 256, NREL);
    k_ddeg<<<ge, 256>>>(edges);
    k_normd<<<1024, 256>>>();
    k_vpass<<<ge, 256>>>(edges);

    k_nodeprep<<<(NN + 255) / 256, 256>>>();

    k_wpass<<<ge, 256>>>(edges);

    dim3 gc(1, (NN + CH - 1) / CH, 5);
    k_colsum<<<gc, 256>>>(xs, xf, xm, xn, xp);

    k_combine<<<dim3(NREL, 4), HH>>>(w1s, w1f, w1m, w1n, w1p, b1);
    k_mpart<<<NREL, HH>>>(W2);
    k_fc<<<1, HH>>>(b2, Wfc, bfc, out);
}